// round 8
// baseline (speedup 1.0000x reference)
#include <cuda_runtime.h>
#include <cuda_bf16.h>

#define N_NODES 10000
#define NQUERY  65536

typedef unsigned long long u64;

// packed f32x2 helpers (sm_103a FFMA2 path — only reachable via PTX)
__device__ __forceinline__ u64 fma2(u64 a, u64 b, u64 c) {
    u64 r; asm("fma.rn.f32x2 %0, %1, %2, %3;" : "=l"(r) : "l"(a), "l"(b), "l"(c)); return r;
}
__device__ __forceinline__ u64 mul2(u64 a, u64 b) {
    u64 r; asm("mul.rn.f32x2 %0, %1, %2;" : "=l"(r) : "l"(a), "l"(b)); return r;
}
__device__ __forceinline__ float hadd2(u64 a) {
    unsigned lo, hi;
    asm("mov.b64 {%0, %1}, %2;" : "=r"(lo), "=r"(hi) : "l"(a));
    return __uint_as_float(lo) + __uint_as_float(hi);
}

#define NEG1X2 0xBF800000BF800000ULL   // packed (-1.0f, -1.0f)

__global__ __launch_bounds__(256, 5)
void madgraph_kernel(const int* __restrict__ src,
                     const int* __restrict__ dst,
                     const int* __restrict__ mid0,
                     const int* __restrict__ mid1,
                     const float* __restrict__ position,
                     const float* __restrict__ src_field,
                     const float* __restrict__ dst_field,
                     const float* __restrict__ unc,
                     const float* __restrict__ edge,
                     float* __restrict__ out)
{
    const unsigned FULL = 0xFFFFFFFFu;
    const int warp = (blockIdx.x * blockDim.x + threadIdx.x) >> 5;
    const int lane = threadIdx.x & 31;
    const int n = warp;

    const int s_node = __ldg(&src[n]);
    const int d_node = __ldg(&dst[n]);

    // Lane l<8 holds mid0[n][l]; lanes 8..15 hold mid1[n][l-8].
    int m_own = 0;
    if (lane < 8)        m_own = __ldg(&mid0[n * 8 + lane]);
    else if (lane < 16)  m_own = __ldg(&mid1[n * 8 + (lane - 8)]);

    // Edge value (DRAM-resident 400MB table) — issue ASAP, consumed at the end.
    float ev_own = 0.f;
    if (lane < 16) {
        const int eidx = (lane < 8) ? (m_own * N_NODES + d_node)    // edge[mid0[s], dst]
                                    : (s_node * N_NODES + m_own);   // edge[src, mid1[s]]
        ev_own = __ldg(&edge[eidx]);
    }
    const float u = __ldg(unc);

    // Each lane owns dims [4*lane .. 4*lane+3] of a 128-dim row,
    // viewed as two packed f32x2 pairs (.x = dims 0-1, .y = dims 2-3).
    const ulonglong2* pos2 = (const ulonglong2*)position;
    const ulonglong2* sf2  = (const ulonglong2*)src_field;
    const ulonglong2* df2  = (const ulonglong2*)dst_field;

    float D1, D2;

    // ---- pass 1: samples 0..7 (base = pos[src], field = dst_field[dst]) ----
    {
        const ulonglong2 base = __ldg(&pos2[s_node * 32 + lane]);
        const ulonglong2 f    = __ldg(&df2 [d_node * 32 + lane]);
        int mm[8];
        #pragma unroll
        for (int s = 0; s < 8; ++s) mm[s] = __shfl_sync(FULL, m_own, s);
        ulonglong2 pm[8];
        #pragma unroll
        for (int s = 0; s < 8; ++s) pm[s] = __ldg(&pos2[mm[s] * 32 + lane]);
        float V[16];
        #pragma unroll
        for (int s = 0; s < 8; ++s) {
            const u64 d01 = fma2(pm[s].x, NEG1X2, base.x);   // base - pm
            const u64 d23 = fma2(pm[s].y, NEG1X2, base.y);
            V[s]     = hadd2(fma2(d23, f.y,  mul2(d01, f.x)));   // dot partial
            V[8 + s] = hadd2(fma2(d23, d23,  mul2(d01, d01)));   // |d|^2 partial
        }
        // 16-value butterfly: lane l ends with total for value index l
        // (lanes 0-15: dots, lanes 16-31: norms)
        #pragma unroll
        for (int m = 16, cnt = 16; m >= 2; m >>= 1, cnt >>= 1) {
            const int  half  = cnt >> 1;
            const bool upper = (lane & m) != 0;
            #pragma unroll
            for (int j = 0; j < 8; ++j) {
                if (j < half) {
                    float send = upper ? V[j] : V[j + half];
                    float recv = __shfl_xor_sync(FULL, send, m);
                    V[j] = (upper ? V[j + half] : V[j]) + recv;
                }
            }
        }
        D1 = V[0] + __shfl_xor_sync(FULL, V[0], 1);
    }

    // ---- pass 2: samples 8..15 (base = pos[dst], field = src_field[src]) ----
    {
        const ulonglong2 base = __ldg(&pos2[d_node * 32 + lane]);
        const ulonglong2 f    = __ldg(&sf2 [s_node * 32 + lane]);
        int mm[8];
        #pragma unroll
        for (int s = 0; s < 8; ++s) mm[s] = __shfl_sync(FULL, m_own, 8 + s);
        ulonglong2 pm[8];
        #pragma unroll
        for (int s = 0; s < 8; ++s) pm[s] = __ldg(&pos2[mm[s] * 32 + lane]);
        float V[16];
        #pragma unroll
        for (int s = 0; s < 8; ++s) {
            const u64 d01 = fma2(pm[s].x, NEG1X2, base.x);
            const u64 d23 = fma2(pm[s].y, NEG1X2, base.y);
            V[s]     = hadd2(fma2(d23, f.y,  mul2(d01, f.x)));
            V[8 + s] = hadd2(fma2(d23, d23,  mul2(d01, d01)));
        }
        #pragma unroll
        for (int m = 16, cnt = 16; m >= 2; m >>= 1, cnt >>= 1) {
            const int  half  = cnt >> 1;
            const bool upper = (lane & m) != 0;
            #pragma unroll
            for (int j = 0; j < 8; ++j) {
                if (j < half) {
                    float send = upper ? V[j] : V[j + half];
                    float recv = __shfl_xor_sync(FULL, send, m);
                    V[j] = (upper ? V[j + half] : V[j]) + recv;
                }
            }
        }
        D2 = V[0] + __shfl_xor_sync(FULL, V[0], 1);
    }

    // Lanes 16..31 hold squared norms; hand them to lanes 0..15.
    const float M1 = __shfl_xor_sync(FULL, D1, 16);
    const float M2 = __shfl_xor_sync(FULL, D2, 16);

    // Slot layout: even lanes (<16) own pass-1 sample (l>>1); odd own pass-2 sample 8+(l>>1).
    const int  odd  = lane & 1;
    const int  samp = (lane >> 1) | (odd ? 8 : 0);
    const float ev  = __shfl_sync(FULL, ev_own, samp);

    float a, logit;
    if (lane < 16) {
        const float dot = odd ? D2 : D1;
        const float n2  = odd ? M2 : M1;
        logit = dot + u * ev;
        a = 1.0f - sqrtf(n2);
    } else {
        logit = 0.f;
        a = -1e30f;
    }

    // 16-wide softmax among lanes 0..15
    float mx = a;
    #pragma unroll
    for (int o = 8; o > 0; o >>= 1)
        mx = fmaxf(mx, __shfl_xor_sync(FULL, mx, o));

    const float e = (lane < 16) ? __expf(a - mx) : 0.f;
    float num = logit * e;
    float den = e;
    #pragma unroll
    for (int o = 8; o > 0; o >>= 1) {
        num += __shfl_xor_sync(FULL, num, o);
        den += __shfl_xor_sync(FULL, den, o);
    }

    if (lane == 0) out[n] = num / den;
}

extern "C" void kernel_launch(void* const* d_in, const int* in_sizes, int n_in,
                              void* d_out, int out_size)
{
    const int*   src      = (const int*)  d_in[0];
    const int*   dst      = (const int*)  d_in[1];
    const int*   mid0     = (const int*)  d_in[2];
    const int*   mid1     = (const int*)  d_in[3];
    const float* position = (const float*)d_in[4];
    const float* src_f    = (const float*)d_in[5];
    const float* dst_f    = (const float*)d_in[6];
    const float* unc      = (const float*)d_in[7];
    const float* edge     = (const float*)d_in[8];
    float*       out      = (float*)      d_out;

    const int blocks = NQUERY / 8;   // 8 warps (queries) per 256-thread block
    madgraph_kernel<<<blocks, 256>>>(src, dst, mid0, mid1, position,
                                     src_f, dst_f, unc, edge, out);
}